// round 12
// baseline (speedup 1.0000x reference)
#include <cuda_runtime.h>
#include <cuda_bf16.h>
#include <cstdint>

// LIF activation, forward:
//   decay[c] = 1 - w_leak[c]
//   gate  = (Vm < 1)  (strict)
//   Vm    = relu(x + decay*Vm*gate)
//   spike = (Vm > 1) ? 1 : 0  (strict)
// B=128, T=1000, C=512.
// R12: R11 (contiguous 1D bulk, grid=128, 512 thr) with bigger bursts:
// CHUNK_T=25 -> 51.2KB contiguous transfers, 40 chunks (20% less
// orchestration). IN ring 2 stages + OUT ring 2 stages = 204.8KB smem.
// Refill-before-compute keeps ~2 chunks of reads in flight (same effective
// depth as R11's steady state).

namespace {
constexpr int B = 128;
constexpr int T = 1000;
constexpr int C = 512;
constexpr int CHUNK_T = 25;                        // timesteps per chunk
constexpr int NCHUNKS = T / CHUNK_T;               // 40
constexpr uint32_t CH_BYTES = CHUNK_T * C * 4;     // 51200
constexpr int IN_STAGES  = 2;
constexpr int OUT_STAGES = 2;
constexpr int THREADS = C;                         // 512, one per channel

constexpr uint32_t SMEM_IN   = 0;
constexpr uint32_t SMEM_OUT  = IN_STAGES * CH_BYTES;               // 102400
constexpr uint32_t SMEM_MBAR = SMEM_OUT + OUT_STAGES * CH_BYTES;   // 204800
constexpr uint32_t SMEM_TOTAL = SMEM_MBAR + IN_STAGES * 8 + 64;
}

__device__ __forceinline__ uint32_t smem_u32(const void* p) {
    uint32_t a;
    asm("{ .reg .u64 t; cvta.to.shared.u64 t, %1; cvt.u32.u64 %0, t; }" : "=r"(a) : "l"(p));
    return a;
}
__device__ __forceinline__ void mbar_init(uint32_t mbar, uint32_t cnt) {
    asm volatile("mbarrier.init.shared.b64 [%0], %1;" :: "r"(mbar), "r"(cnt) : "memory");
}
__device__ __forceinline__ void mbar_expect_tx(uint32_t mbar, uint32_t bytes) {
    asm volatile("mbarrier.arrive.expect_tx.shared.b64 _, [%0], %1;" :: "r"(mbar), "r"(bytes) : "memory");
}
__device__ __forceinline__ void mbar_wait(uint32_t mbar, uint32_t parity) {
    uint32_t done;
    asm volatile(
        "{\n\t.reg .pred p;\n\t"
        "mbarrier.try_wait.parity.acquire.cta.shared::cta.b64 p, [%1], %2;\n\t"
        "selp.b32 %0, 1, 0, p;\n\t}"
        : "=r"(done) : "r"(mbar), "r"(parity) : "memory");
    while (!done) {
        asm volatile(
            "{\n\t.reg .pred p;\n\t"
            "mbarrier.try_wait.parity.acquire.cta.shared::cta.b64 p, [%1], %2, 0x989680;\n\t"
            "selp.b32 %0, 1, 0, p;\n\t}"
            : "=r"(done) : "r"(mbar), "r"(parity) : "memory");
    }
}
__device__ __forceinline__ void bulk_load(uint32_t smem_dst, const void* gmem_src,
                                          uint32_t bytes, uint32_t mbar) {
    asm volatile(
        "cp.async.bulk.shared::cta.global.mbarrier::complete_tx::bytes [%0], [%1], %2, [%3];"
        :: "r"(smem_dst), "l"(gmem_src), "r"(bytes), "r"(mbar) : "memory");
}
__device__ __forceinline__ void bulk_store(void* gmem_dst, uint32_t smem_src, uint32_t bytes) {
    asm volatile(
        "cp.async.bulk.global.shared::cta.bulk_group [%0], [%1], %2;"
        :: "l"(gmem_dst), "r"(smem_src), "r"(bytes) : "memory");
}

__global__ void __launch_bounds__(THREADS, 1)
lif_kernel(const float* __restrict__ x,
           const float* __restrict__ wl,
           float* __restrict__ out)
{
    extern __shared__ __align__(1024) char smem[];
    const uint32_t sbase = smem_u32(smem);
    const int tid = threadIdx.x;
    const int b   = blockIdx.x;
    const int c   = tid;                       // one thread per channel

    const float d = 1.0f - wl[c];
    float v = 0.0f;

    const float* __restrict__ xslab = x   + (size_t)b * T * C;   // 2MB contiguous
    float*       __restrict__ oslab = out + (size_t)b * T * C;

    if (tid == 0) {
        #pragma unroll
        for (int s = 0; s < IN_STAGES; s++)
            mbar_init(sbase + SMEM_MBAR + s * 8, 1);
    }
    __syncthreads();

    // Prologue: fill both IN stages (chunks 0..1) — 102KB of reads in flight.
    if (tid == 0) {
        #pragma unroll
        for (int s = 0; s < IN_STAGES; s++) {
            const uint32_t mbar = sbase + SMEM_MBAR + s * 8;
            mbar_expect_tx(mbar, CH_BYTES);
            bulk_load(sbase + SMEM_IN + s * CH_BYTES,
                      xslab + (size_t)s * CHUNK_T * C, CH_BYTES, mbar);
        }
    }

    int s = 0, parity = 0;
    for (int i = 0; i < NCHUNKS; i++) {
        const int o = i & (OUT_STAGES - 1);
        const uint32_t mbar = sbase + SMEM_MBAR + s * 8;

        // 1) Wait for input chunk i, pull this thread's column to registers.
        mbar_wait(mbar, (uint32_t)parity);

        const float* sin = (const float*)(smem + SMEM_IN + s * CH_BYTES);
        float xv[CHUNK_T];
        #pragma unroll
        for (int u = 0; u < CHUNK_T; u++)
            xv[u] = sin[u * C + c];

        // 2) One sync covers: (a) all threads consumed smem-in stage s,
        //    (b) tid0's drain of the out-buffer we're about to overwrite.
        if (tid == 0)
            asm volatile("cp.async.bulk.wait_group.read 1;" ::: "memory");
        __syncthreads();

        // 3) Refill the consumed in-stage immediately (loads run during compute).
        if (tid == 0) {
            const int nxt = i + IN_STAGES;
            if (nxt < NCHUNKS) {
                mbar_expect_tx(mbar, CH_BYTES);
                bulk_load(sbase + SMEM_IN + s * CH_BYTES,
                          xslab + (size_t)nxt * CHUNK_T * C, CH_BYTES, mbar);
            }
        }

        // 4) Serial recurrence, spikes into the out smem buffer.
        float* sout = (float*)(smem + SMEM_OUT + o * CH_BYTES);
        #pragma unroll
        for (int u = 0; u < CHUNK_T; u++) {
            v = fmaxf(0.0f, xv[u] + (v < 1.0f ? d * v : 0.0f));
            sout[u * C + c] = (v > 1.0f) ? 1.0f : 0.0f;
        }

        __syncthreads();   // all spikes for chunk i in smem

        // 5) Bulk-store the chunk: one 51.2KB fully-contiguous write burst.
        if (tid == 0) {
            asm volatile("fence.proxy.async.shared::cta;" ::: "memory");
            bulk_store(oslab + (size_t)i * CHUNK_T * C,
                       sbase + SMEM_OUT + o * CH_BYTES, CH_BYTES);
            asm volatile("cp.async.bulk.commit_group;" ::: "memory");
        }

        if (++s == IN_STAGES) { s = 0; parity ^= 1; }
    }

    if (tid == 0)
        asm volatile("cp.async.bulk.wait_group 0;" ::: "memory");
}

extern "C" void kernel_launch(void* const* d_in, const int* in_sizes, int n_in,
                              void* d_out, int out_size)
{
    const float* x  = (const float*)d_in[0];   // x [B,T,C]
    const float* wl = (const float*)d_in[1];   // w_leak [C]
    float* out      = (float*)d_out;

    cudaFuncSetAttribute(lif_kernel, cudaFuncAttributeMaxDynamicSharedMemorySize,
                         (int)SMEM_TOTAL);
    lif_kernel<<<B, THREADS, SMEM_TOTAL>>>(x, wl, out);
}

// round 13
// speedup vs baseline: 1.0011x; 1.0011x over previous
#include <cuda_runtime.h>
#include <cuda_bf16.h>
#include <cstdint>

// LIF activation, forward:
//   decay[c] = 1 - w_leak[c]
//   gate  = (Vm < 1)  (strict)
//   Vm    = relu(x + decay*Vm*gate)
//   spike = (Vm > 1) ? 1 : 0  (strict)
// B=128, T=1000, C=512.
// R13: R11 (best: contiguous 1D bulk, grid=128, 512 thr, CHUNK_T=20,
// IN 3 / OUT 2) with the out-drain moved from the top of the iteration to
// right after commit_group: the wait_group.read now overlaps the NEXT
// chunk's mbarrier wait instead of blocking the whole CTA after it.

namespace {
constexpr int B = 128;
constexpr int T = 1000;
constexpr int C = 512;
constexpr int CHUNK_T = 20;                        // timesteps per chunk
constexpr int NCHUNKS = T / CHUNK_T;               // 50
constexpr uint32_t CH_BYTES = CHUNK_T * C * 4;     // 40960
constexpr int IN_STAGES  = 3;
constexpr int OUT_STAGES = 2;
constexpr int THREADS = C;                         // 512, one per channel

constexpr uint32_t SMEM_IN   = 0;
constexpr uint32_t SMEM_OUT  = IN_STAGES * CH_BYTES;               // 122880
constexpr uint32_t SMEM_MBAR = SMEM_OUT + OUT_STAGES * CH_BYTES;   // 204800
constexpr uint32_t SMEM_TOTAL = SMEM_MBAR + IN_STAGES * 8 + 64;    // ~205KB
}

__device__ __forceinline__ uint32_t smem_u32(const void* p) {
    uint32_t a;
    asm("{ .reg .u64 t; cvta.to.shared.u64 t, %1; cvt.u32.u64 %0, t; }" : "=r"(a) : "l"(p));
    return a;
}
__device__ __forceinline__ void mbar_init(uint32_t mbar, uint32_t cnt) {
    asm volatile("mbarrier.init.shared.b64 [%0], %1;" :: "r"(mbar), "r"(cnt) : "memory");
}
__device__ __forceinline__ void mbar_expect_tx(uint32_t mbar, uint32_t bytes) {
    asm volatile("mbarrier.arrive.expect_tx.shared.b64 _, [%0], %1;" :: "r"(mbar), "r"(bytes) : "memory");
}
__device__ __forceinline__ void mbar_wait(uint32_t mbar, uint32_t parity) {
    uint32_t done;
    asm volatile(
        "{\n\t.reg .pred p;\n\t"
        "mbarrier.try_wait.parity.acquire.cta.shared::cta.b64 p, [%1], %2;\n\t"
        "selp.b32 %0, 1, 0, p;\n\t}"
        : "=r"(done) : "r"(mbar), "r"(parity) : "memory");
    while (!done) {
        asm volatile(
            "{\n\t.reg .pred p;\n\t"
            "mbarrier.try_wait.parity.acquire.cta.shared::cta.b64 p, [%1], %2, 0x989680;\n\t"
            "selp.b32 %0, 1, 0, p;\n\t}"
            : "=r"(done) : "r"(mbar), "r"(parity) : "memory");
    }
}
__device__ __forceinline__ void bulk_load(uint32_t smem_dst, const void* gmem_src,
                                          uint32_t bytes, uint32_t mbar) {
    asm volatile(
        "cp.async.bulk.shared::cta.global.mbarrier::complete_tx::bytes [%0], [%1], %2, [%3];"
        :: "r"(smem_dst), "l"(gmem_src), "r"(bytes), "r"(mbar) : "memory");
}
__device__ __forceinline__ void bulk_store(void* gmem_dst, uint32_t smem_src, uint32_t bytes) {
    asm volatile(
        "cp.async.bulk.global.shared::cta.bulk_group [%0], [%1], %2;"
        :: "l"(gmem_dst), "r"(smem_src), "r"(bytes) : "memory");
}

__global__ void __launch_bounds__(THREADS, 1)
lif_kernel(const float* __restrict__ x,
           const float* __restrict__ wl,
           float* __restrict__ out)
{
    extern __shared__ __align__(1024) char smem[];
    const uint32_t sbase = smem_u32(smem);
    const int tid = threadIdx.x;
    const int b   = blockIdx.x;
    const int c   = tid;                       // one thread per channel

    const float d = 1.0f - wl[c];
    float v = 0.0f;

    const float* __restrict__ xslab = x   + (size_t)b * T * C;   // 2MB contiguous
    float*       __restrict__ oslab = out + (size_t)b * T * C;

    if (tid == 0) {
        #pragma unroll
        for (int s = 0; s < IN_STAGES; s++)
            mbar_init(sbase + SMEM_MBAR + s * 8, 1);
    }
    __syncthreads();

    // Prologue: fill the IN ring (chunks 0..2) — 120KB of contiguous reads in flight.
    if (tid == 0) {
        #pragma unroll
        for (int s = 0; s < IN_STAGES; s++) {
            const uint32_t mbar = sbase + SMEM_MBAR + s * 8;
            mbar_expect_tx(mbar, CH_BYTES);
            bulk_load(sbase + SMEM_IN + s * CH_BYTES,
                      xslab + (size_t)s * CHUNK_T * C, CH_BYTES, mbar);
        }
    }

    int s = 0, parity = 0;
    for (int i = 0; i < NCHUNKS; i++) {
        const int o = i & (OUT_STAGES - 1);
        const uint32_t mbar = sbase + SMEM_MBAR + s * 8;

        // 1) Wait for input chunk i, pull this thread's column to registers.
        //    (tid0's end-of-previous-iteration drain overlapped with this wait.)
        mbar_wait(mbar, (uint32_t)parity);

        const float* sin = (const float*)(smem + SMEM_IN + s * CH_BYTES);
        float xv[CHUNK_T];
        #pragma unroll
        for (int u = 0; u < CHUNK_T; u++)
            xv[u] = sin[u * C + c];

        // 2) Sync: (a) all threads consumed smem-in stage s, (b) tid0's drain
        //    of the OUT buffer (done at the end of iteration i-1) is ordered
        //    before everyone's sout writes below.
        __syncthreads();

        // 3) Refill the consumed in-stage immediately (loads run during compute).
        if (tid == 0) {
            const int nxt = i + IN_STAGES;
            if (nxt < NCHUNKS) {
                mbar_expect_tx(mbar, CH_BYTES);
                bulk_load(sbase + SMEM_IN + s * CH_BYTES,
                          xslab + (size_t)nxt * CHUNK_T * C, CH_BYTES, mbar);
            }
        }

        // 4) Serial recurrence, spikes into the out smem buffer.
        float* sout = (float*)(smem + SMEM_OUT + o * CH_BYTES);
        #pragma unroll
        for (int u = 0; u < CHUNK_T; u++) {
            v = fmaxf(0.0f, xv[u] + (v < 1.0f ? d * v : 0.0f));
            sout[u * C + c] = (v > 1.0f) ? 1.0f : 0.0f;
        }

        __syncthreads();   // all spikes for chunk i in smem

        // 5) Bulk-store the chunk, then drain the PREVIOUS store's smem reads
        //    now — this wait overlaps the next chunk's mbarrier wait, keeping
        //    it off the critical path.
        if (tid == 0) {
            asm volatile("fence.proxy.async.shared::cta;" ::: "memory");
            bulk_store(oslab + (size_t)i * CHUNK_T * C,
                       sbase + SMEM_OUT + o * CH_BYTES, CH_BYTES);
            asm volatile("cp.async.bulk.commit_group;" ::: "memory");
            asm volatile("cp.async.bulk.wait_group.read 1;" ::: "memory");
        }

        if (++s == IN_STAGES) { s = 0; parity ^= 1; }
    }

    if (tid == 0)
        asm volatile("cp.async.bulk.wait_group 0;" ::: "memory");
}

extern "C" void kernel_launch(void* const* d_in, const int* in_sizes, int n_in,
                              void* d_out, int out_size)
{
    const float* x  = (const float*)d_in[0];   // x [B,T,C]
    const float* wl = (const float*)d_in[1];   // w_leak [C]
    float* out      = (float*)d_out;

    cudaFuncSetAttribute(lif_kernel, cudaFuncAttributeMaxDynamicSharedMemorySize,
                         (int)SMEM_TOTAL);
    lif_kernel<<<B, THREADS, SMEM_TOTAL>>>(x, wl, out);
}

// round 14
// speedup vs baseline: 1.0021x; 1.0011x over previous
#include <cuda_runtime.h>
#include <cuda_bf16.h>
#include <cstdint>

// LIF activation, forward:
//   decay[c] = 1 - w_leak[c]
//   gate  = (Vm < 1)  (strict)
//   Vm    = relu(x + decay*Vm*gate)
//   spike = (Vm > 1) ? 1 : 0  (strict)
// B=128, T=1000, C=512.
// R14 == R11 (session best, 89.7us / 77.7% DRAM): fully-contiguous 1D
// bulk-async streaming. grid=128 (one CTA per batch), 512 threads (one per
// channel), CHUNK_T=20 -> 40KB contiguous transfers, IN ring 3 stages +
// OUT ring 2 stages, drain folded into the consume-sync, refill issued
// before the serial recurrence. Pinned at the DRAM r/w-mix ceiling:
// 9 architectures bracket 73.5-77.7% of spec HBM; this is the max.

namespace {
constexpr int B = 128;
constexpr int T = 1000;
constexpr int C = 512;
constexpr int CHUNK_T = 20;                        // timesteps per chunk
constexpr int NCHUNKS = T / CHUNK_T;               // 50
constexpr uint32_t CH_BYTES = CHUNK_T * C * 4;     // 40960
constexpr int IN_STAGES  = 3;
constexpr int OUT_STAGES = 2;
constexpr int THREADS = C;                         // 512, one per channel

constexpr uint32_t SMEM_IN   = 0;
constexpr uint32_t SMEM_OUT  = IN_STAGES * CH_BYTES;               // 122880
constexpr uint32_t SMEM_MBAR = SMEM_OUT + OUT_STAGES * CH_BYTES;   // 204800
constexpr uint32_t SMEM_TOTAL = SMEM_MBAR + IN_STAGES * 8 + 64;    // ~205KB
}

__device__ __forceinline__ uint32_t smem_u32(const void* p) {
    uint32_t a;
    asm("{ .reg .u64 t; cvta.to.shared.u64 t, %1; cvt.u32.u64 %0, t; }" : "=r"(a) : "l"(p));
    return a;
}
__device__ __forceinline__ void mbar_init(uint32_t mbar, uint32_t cnt) {
    asm volatile("mbarrier.init.shared.b64 [%0], %1;" :: "r"(mbar), "r"(cnt) : "memory");
}
__device__ __forceinline__ void mbar_expect_tx(uint32_t mbar, uint32_t bytes) {
    asm volatile("mbarrier.arrive.expect_tx.shared.b64 _, [%0], %1;" :: "r"(mbar), "r"(bytes) : "memory");
}
__device__ __forceinline__ void mbar_wait(uint32_t mbar, uint32_t parity) {
    uint32_t done;
    asm volatile(
        "{\n\t.reg .pred p;\n\t"
        "mbarrier.try_wait.parity.acquire.cta.shared::cta.b64 p, [%1], %2;\n\t"
        "selp.b32 %0, 1, 0, p;\n\t}"
        : "=r"(done) : "r"(mbar), "r"(parity) : "memory");
    while (!done) {
        asm volatile(
            "{\n\t.reg .pred p;\n\t"
            "mbarrier.try_wait.parity.acquire.cta.shared::cta.b64 p, [%1], %2, 0x989680;\n\t"
            "selp.b32 %0, 1, 0, p;\n\t}"
            : "=r"(done) : "r"(mbar), "r"(parity) : "memory");
    }
}
__device__ __forceinline__ void bulk_load(uint32_t smem_dst, const void* gmem_src,
                                          uint32_t bytes, uint32_t mbar) {
    asm volatile(
        "cp.async.bulk.shared::cta.global.mbarrier::complete_tx::bytes [%0], [%1], %2, [%3];"
        :: "r"(smem_dst), "l"(gmem_src), "r"(bytes), "r"(mbar) : "memory");
}
__device__ __forceinline__ void bulk_store(void* gmem_dst, uint32_t smem_src, uint32_t bytes) {
    asm volatile(
        "cp.async.bulk.global.shared::cta.bulk_group [%0], [%1], %2;"
        :: "l"(gmem_dst), "r"(smem_src), "r"(bytes) : "memory");
}

__global__ void __launch_bounds__(THREADS, 1)
lif_kernel(const float* __restrict__ x,
           const float* __restrict__ wl,
           float* __restrict__ out)
{
    extern __shared__ __align__(1024) char smem[];
    const uint32_t sbase = smem_u32(smem);
    const int tid = threadIdx.x;
    const int b   = blockIdx.x;
    const int c   = tid;                       // one thread per channel

    const float d = 1.0f - wl[c];
    float v = 0.0f;

    const float* __restrict__ xslab = x   + (size_t)b * T * C;   // 2MB contiguous
    float*       __restrict__ oslab = out + (size_t)b * T * C;

    if (tid == 0) {
        #pragma unroll
        for (int s = 0; s < IN_STAGES; s++)
            mbar_init(sbase + SMEM_MBAR + s * 8, 1);
    }
    __syncthreads();

    // Prologue: fill the IN ring (chunks 0..2) — 120KB of contiguous reads in flight.
    if (tid == 0) {
        #pragma unroll
        for (int s = 0; s < IN_STAGES; s++) {
            const uint32_t mbar = sbase + SMEM_MBAR + s * 8;
            mbar_expect_tx(mbar, CH_BYTES);
            bulk_load(sbase + SMEM_IN + s * CH_BYTES,
                      xslab + (size_t)s * CHUNK_T * C, CH_BYTES, mbar);
        }
    }

    int s = 0, parity = 0;
    for (int i = 0; i < NCHUNKS; i++) {
        const int o = i & (OUT_STAGES - 1);
        const uint32_t mbar = sbase + SMEM_MBAR + s * 8;

        // 1) Wait for input chunk i, pull this thread's column to registers.
        mbar_wait(mbar, (uint32_t)parity);

        const float* sin = (const float*)(smem + SMEM_IN + s * CH_BYTES);
        float xv[CHUNK_T];
        #pragma unroll
        for (int u = 0; u < CHUNK_T; u++)
            xv[u] = sin[u * C + c];

        // 2) One sync covers: (a) all threads consumed smem-in stage s,
        //    (b) tid0's drain of the out-buffer we're about to overwrite.
        if (tid == 0)
            asm volatile("cp.async.bulk.wait_group.read 1;" ::: "memory");
        __syncthreads();

        // 3) Refill the consumed in-stage immediately (loads run during compute).
        if (tid == 0) {
            const int nxt = i + IN_STAGES;
            if (nxt < NCHUNKS) {
                mbar_expect_tx(mbar, CH_BYTES);
                bulk_load(sbase + SMEM_IN + s * CH_BYTES,
                          xslab + (size_t)nxt * CHUNK_T * C, CH_BYTES, mbar);
            }
        }

        // 4) Serial recurrence, spikes into the out smem buffer.
        float* sout = (float*)(smem + SMEM_OUT + o * CH_BYTES);
        #pragma unroll
        for (int u = 0; u < CHUNK_T; u++) {
            v = fmaxf(0.0f, xv[u] + (v < 1.0f ? d * v : 0.0f));
            sout[u * C + c] = (v > 1.0f) ? 1.0f : 0.0f;
        }

        __syncthreads();   // all spikes for chunk i in smem

        // 5) Bulk-store the chunk: one 40KB fully-contiguous write burst.
        if (tid == 0) {
            asm volatile("fence.proxy.async.shared::cta;" ::: "memory");
            bulk_store(oslab + (size_t)i * CHUNK_T * C,
                       sbase + SMEM_OUT + o * CH_BYTES, CH_BYTES);
            asm volatile("cp.async.bulk.commit_group;" ::: "memory");
        }

        if (++s == IN_STAGES) { s = 0; parity ^= 1; }
    }

    if (tid == 0)
        asm volatile("cp.async.bulk.wait_group 0;" ::: "memory");
}

extern "C" void kernel_launch(void* const* d_in, const int* in_sizes, int n_in,
                              void* d_out, int out_size)
{
    const float* x  = (const float*)d_in[0];   // x [B,T,C]
    const float* wl = (const float*)d_in[1];   // w_leak [C]
    float* out      = (float*)d_out;

    cudaFuncSetAttribute(lif_kernel, cudaFuncAttributeMaxDynamicSharedMemorySize,
                         (int)SMEM_TOTAL);
    lif_kernel<<<B, THREADS, SMEM_TOTAL>>>(x, wl, out);
}

// round 15
// speedup vs baseline: 1.0159x; 1.0137x over previous
#include <cuda_runtime.h>
#include <cuda_bf16.h>
#include <cstdint>

// LIF activation, forward:
//   decay[c] = 1 - w_leak[c]
//   gate  = (Vm < 1)  (strict)
//   Vm    = relu(x + decay*Vm*gate)
//   spike = (Vm > 1) ? 1 : 0  (strict)
// B=128, T=1000, C=512.
//
// FINAL (R11 config, session best 89.66us / 6159 GB/s):
// Fully-contiguous 1D bulk-async (TMA-engine) streaming in BOTH directions.
//   - grid=128 (one CTA per batch b; slab x[b] = 2MB contiguous)
//   - 512 threads, one per channel; the T-recurrence is serial per thread
//   - CHUNK_T=20 -> 40KB contiguous transfers (longest DRAM burst runs)
//   - IN ring 3 stages + OUT ring 2 stages (~205KB smem, 1 CTA/SM)
//   - out-drain folded into the consume-sync; refill issued before compute
// Why this shape: the per-SM LDG/L1tex outstanding-request cap limits
// LDG/STG streaming to ~4.3 TB/s on sm_103a; cp.async.bulk bypasses it
// (R4: +26%). Beyond that the kernel sits at the DRAM r/w-mix ceiling
// (74-78% of spec across 9 measured architectures) with minimum traffic,
// so no further data-path or scheduling change moves it.

namespace {
constexpr int B = 128;
constexpr int T = 1000;
constexpr int C = 512;
constexpr int CHUNK_T = 20;                        // timesteps per chunk
constexpr int NCHUNKS = T / CHUNK_T;               // 50
constexpr uint32_t CH_BYTES = CHUNK_T * C * 4;     // 40960
constexpr int IN_STAGES  = 3;
constexpr int OUT_STAGES = 2;
constexpr int THREADS = C;                         // 512, one per channel

constexpr uint32_t SMEM_IN   = 0;
constexpr uint32_t SMEM_OUT  = IN_STAGES * CH_BYTES;               // 122880
constexpr uint32_t SMEM_MBAR = SMEM_OUT + OUT_STAGES * CH_BYTES;   // 204800
constexpr uint32_t SMEM_TOTAL = SMEM_MBAR + IN_STAGES * 8 + 64;    // ~205KB
}

__device__ __forceinline__ uint32_t smem_u32(const void* p) {
    uint32_t a;
    asm("{ .reg .u64 t; cvta.to.shared.u64 t, %1; cvt.u32.u64 %0, t; }" : "=r"(a) : "l"(p));
    return a;
}
__device__ __forceinline__ void mbar_init(uint32_t mbar, uint32_t cnt) {
    asm volatile("mbarrier.init.shared.b64 [%0], %1;" :: "r"(mbar), "r"(cnt) : "memory");
}
__device__ __forceinline__ void mbar_expect_tx(uint32_t mbar, uint32_t bytes) {
    asm volatile("mbarrier.arrive.expect_tx.shared.b64 _, [%0], %1;" :: "r"(mbar), "r"(bytes) : "memory");
}
__device__ __forceinline__ void mbar_wait(uint32_t mbar, uint32_t parity) {
    uint32_t done;
    asm volatile(
        "{\n\t.reg .pred p;\n\t"
        "mbarrier.try_wait.parity.acquire.cta.shared::cta.b64 p, [%1], %2;\n\t"
        "selp.b32 %0, 1, 0, p;\n\t}"
        : "=r"(done) : "r"(mbar), "r"(parity) : "memory");
    while (!done) {
        asm volatile(
            "{\n\t.reg .pred p;\n\t"
            "mbarrier.try_wait.parity.acquire.cta.shared::cta.b64 p, [%1], %2, 0x989680;\n\t"
            "selp.b32 %0, 1, 0, p;\n\t}"
            : "=r"(done) : "r"(mbar), "r"(parity) : "memory");
    }
}
__device__ __forceinline__ void bulk_load(uint32_t smem_dst, const void* gmem_src,
                                          uint32_t bytes, uint32_t mbar) {
    asm volatile(
        "cp.async.bulk.shared::cta.global.mbarrier::complete_tx::bytes [%0], [%1], %2, [%3];"
        :: "r"(smem_dst), "l"(gmem_src), "r"(bytes), "r"(mbar) : "memory");
}
__device__ __forceinline__ void bulk_store(void* gmem_dst, uint32_t smem_src, uint32_t bytes) {
    asm volatile(
        "cp.async.bulk.global.shared::cta.bulk_group [%0], [%1], %2;"
        :: "l"(gmem_dst), "r"(smem_src), "r"(bytes) : "memory");
}

__global__ void __launch_bounds__(THREADS, 1)
lif_kernel(const float* __restrict__ x,
           const float* __restrict__ wl,
           float* __restrict__ out)
{
    extern __shared__ __align__(1024) char smem[];
    const uint32_t sbase = smem_u32(smem);
    const int tid = threadIdx.x;
    const int b   = blockIdx.x;
    const int c   = tid;                       // one thread per channel

    const float d = 1.0f - wl[c];
    float v = 0.0f;

    const float* __restrict__ xslab = x   + (size_t)b * T * C;   // 2MB contiguous
    float*       __restrict__ oslab = out + (size_t)b * T * C;

    if (tid == 0) {
        #pragma unroll
        for (int s = 0; s < IN_STAGES; s++)
            mbar_init(sbase + SMEM_MBAR + s * 8, 1);
    }
    __syncthreads();

    // Prologue: fill the IN ring (chunks 0..2) — 120KB of contiguous reads in flight.
    if (tid == 0) {
        #pragma unroll
        for (int s = 0; s < IN_STAGES; s++) {
            const uint32_t mbar = sbase + SMEM_MBAR + s * 8;
            mbar_expect_tx(mbar, CH_BYTES);
            bulk_load(sbase + SMEM_IN + s * CH_BYTES,
                      xslab + (size_t)s * CHUNK_T * C, CH_BYTES, mbar);
        }
    }

    int s = 0, parity = 0;
    for (int i = 0; i < NCHUNKS; i++) {
        const int o = i & (OUT_STAGES - 1);
        const uint32_t mbar = sbase + SMEM_MBAR + s * 8;

        // 1) Wait for input chunk i, pull this thread's column to registers.
        mbar_wait(mbar, (uint32_t)parity);

        const float* sin = (const float*)(smem + SMEM_IN + s * CH_BYTES);
        float xv[CHUNK_T];
        #pragma unroll
        for (int u = 0; u < CHUNK_T; u++)
            xv[u] = sin[u * C + c];

        // 2) One sync covers: (a) all threads consumed smem-in stage s,
        //    (b) tid0's drain of the out-buffer we're about to overwrite.
        if (tid == 0)
            asm volatile("cp.async.bulk.wait_group.read 1;" ::: "memory");
        __syncthreads();

        // 3) Refill the consumed in-stage immediately (loads run during compute).
        if (tid == 0) {
            const int nxt = i + IN_STAGES;
            if (nxt < NCHUNKS) {
                mbar_expect_tx(mbar, CH_BYTES);
                bulk_load(sbase + SMEM_IN + s * CH_BYTES,
                          xslab + (size_t)nxt * CHUNK_T * C, CH_BYTES, mbar);
            }
        }

        // 4) Serial recurrence, spikes into the out smem buffer.
        float* sout = (float*)(smem + SMEM_OUT + o * CH_BYTES);
        #pragma unroll
        for (int u = 0; u < CHUNK_T; u++) {
            v = fmaxf(0.0f, xv[u] + (v < 1.0f ? d * v : 0.0f));
            sout[u * C + c] = (v > 1.0f) ? 1.0f : 0.0f;
        }

        __syncthreads();   // all spikes for chunk i in smem

        // 5) Bulk-store the chunk: one 40KB fully-contiguous write burst.
        if (tid == 0) {
            asm volatile("fence.proxy.async.shared::cta;" ::: "memory");
            bulk_store(oslab + (size_t)i * CHUNK_T * C,
                       sbase + SMEM_OUT + o * CH_BYTES, CH_BYTES);
            asm volatile("cp.async.bulk.commit_group;" ::: "memory");
        }

        if (++s == IN_STAGES) { s = 0; parity ^= 1; }
    }

    if (tid == 0)
        asm volatile("cp.async.bulk.wait_group 0;" ::: "memory");
}

extern "C" void kernel_launch(void* const* d_in, const int* in_sizes, int n_in,
                              void* d_out, int out_size)
{
    const float* x  = (const float*)d_in[0];   // x [B,T,C]
    const float* wl = (const float*)d_in[1];   // w_leak [C]
    float* out      = (float*)d_out;

    cudaFuncSetAttribute(lif_kernel, cudaFuncAttributeMaxDynamicSharedMemorySize,
                         (int)SMEM_TOTAL);
    lif_kernel<<<B, THREADS, SMEM_TOTAL>>>(x, wl, out);
}

// round 16
// speedup vs baseline: 1.0232x; 1.0073x over previous
#include <cuda_runtime.h>
#include <cuda_bf16.h>
#include <cstdint>

// LIF activation, forward:
//   decay[c] = 1 - w_leak[c]
//   gate  = (Vm < 1)  (strict)
//   Vm    = relu(x + decay*Vm*gate)
//   spike = (Vm > 1) ? 1 : 0  (strict)
// B=128, T=1000, C=512.
//
// FINAL — locked configuration (best measured 88.83us / 6239 GB/s, 78% of
// spec HBM; run-to-run band 88.8-90.0us on identical binary).
//
// Architecture: fully-contiguous 1D bulk-async (TMA-engine) streaming in
// BOTH directions.
//   - grid=128 (one CTA per batch b; slab x[b] = 2MB contiguous)
//   - 512 threads, one per channel; T-recurrence is serial per thread
//   - CHUNK_T=20 -> 40KB contiguous transfers (longest DRAM burst runs)
//   - IN ring 3 stages + OUT ring 2 stages (~205KB smem, 1 CTA/SM)
//   - out-drain folded into the consume-sync; refill issued before compute
//
// Why this shape (session findings):
//   1. Per-SM LDG/L1tex outstanding-request cap limits LDG/STG streaming to
//      ~4.3 TB/s on sm_103a regardless of occupancy/unroll; cp.async.bulk
//      bypasses it (+26%).
//   2. Fully-contiguous 1D bulk beats strided 2D tensor-map boxes by ~1-2%
//      (longer DRAM burst runs).
//   3. Beyond that the kernel sits at the DRAM read/write-mix ceiling
//      (74-79% of spec across 9 measured architectures) with traffic at the
//      structural minimum (524MB), so no data-path or scheduling change
//      moves it outside noise.

namespace {
constexpr int B = 128;
constexpr int T = 1000;
constexpr int C = 512;
constexpr int CHUNK_T = 20;                        // timesteps per chunk
constexpr int NCHUNKS = T / CHUNK_T;               // 50
constexpr uint32_t CH_BYTES = CHUNK_T * C * 4;     // 40960
constexpr int IN_STAGES  = 3;
constexpr int OUT_STAGES = 2;
constexpr int THREADS = C;                         // 512, one per channel

constexpr uint32_t SMEM_IN   = 0;
constexpr uint32_t SMEM_OUT  = IN_STAGES * CH_BYTES;               // 122880
constexpr uint32_t SMEM_MBAR = SMEM_OUT + OUT_STAGES * CH_BYTES;   // 204800
constexpr uint32_t SMEM_TOTAL = SMEM_MBAR + IN_STAGES * 8 + 64;    // ~205KB
}

__device__ __forceinline__ uint32_t smem_u32(const void* p) {
    uint32_t a;
    asm("{ .reg .u64 t; cvta.to.shared.u64 t, %1; cvt.u32.u64 %0, t; }" : "=r"(a) : "l"(p));
    return a;
}
__device__ __forceinline__ void mbar_init(uint32_t mbar, uint32_t cnt) {
    asm volatile("mbarrier.init.shared.b64 [%0], %1;" :: "r"(mbar), "r"(cnt) : "memory");
}
__device__ __forceinline__ void mbar_expect_tx(uint32_t mbar, uint32_t bytes) {
    asm volatile("mbarrier.arrive.expect_tx.shared.b64 _, [%0], %1;" :: "r"(mbar), "r"(bytes) : "memory");
}
__device__ __forceinline__ void mbar_wait(uint32_t mbar, uint32_t parity) {
    uint32_t done;
    asm volatile(
        "{\n\t.reg .pred p;\n\t"
        "mbarrier.try_wait.parity.acquire.cta.shared::cta.b64 p, [%1], %2;\n\t"
        "selp.b32 %0, 1, 0, p;\n\t}"
        : "=r"(done) : "r"(mbar), "r"(parity) : "memory");
    while (!done) {
        asm volatile(
            "{\n\t.reg .pred p;\n\t"
            "mbarrier.try_wait.parity.acquire.cta.shared::cta.b64 p, [%1], %2, 0x989680;\n\t"
            "selp.b32 %0, 1, 0, p;\n\t}"
            : "=r"(done) : "r"(mbar), "r"(parity) : "memory");
    }
}
__device__ __forceinline__ void bulk_load(uint32_t smem_dst, const void* gmem_src,
                                          uint32_t bytes, uint32_t mbar) {
    asm volatile(
        "cp.async.bulk.shared::cta.global.mbarrier::complete_tx::bytes [%0], [%1], %2, [%3];"
        :: "r"(smem_dst), "l"(gmem_src), "r"(bytes), "r"(mbar) : "memory");
}
__device__ __forceinline__ void bulk_store(void* gmem_dst, uint32_t smem_src, uint32_t bytes) {
    asm volatile(
        "cp.async.bulk.global.shared::cta.bulk_group [%0], [%1], %2;"
        :: "l"(gmem_dst), "r"(smem_src), "r"(bytes) : "memory");
}

__global__ void __launch_bounds__(THREADS, 1)
lif_kernel(const float* __restrict__ x,
           const float* __restrict__ wl,
           float* __restrict__ out)
{
    extern __shared__ __align__(1024) char smem[];
    const uint32_t sbase = smem_u32(smem);
    const int tid = threadIdx.x;
    const int b   = blockIdx.x;
    const int c   = tid;                       // one thread per channel

    const float d = 1.0f - wl[c];
    float v = 0.0f;

    const float* __restrict__ xslab = x   + (size_t)b * T * C;   // 2MB contiguous
    float*       __restrict__ oslab = out + (size_t)b * T * C;

    if (tid == 0) {
        #pragma unroll
        for (int s = 0; s < IN_STAGES; s++)
            mbar_init(sbase + SMEM_MBAR + s * 8, 1);
    }
    __syncthreads();

    // Prologue: fill the IN ring (chunks 0..2) — 120KB of contiguous reads in flight.
    if (tid == 0) {
        #pragma unroll
        for (int s = 0; s < IN_STAGES; s++) {
            const uint32_t mbar = sbase + SMEM_MBAR + s * 8;
            mbar_expect_tx(mbar, CH_BYTES);
            bulk_load(sbase + SMEM_IN + s * CH_BYTES,
                      xslab + (size_t)s * CHUNK_T * C, CH_BYTES, mbar);
        }
    }

    int s = 0, parity = 0;
    for (int i = 0; i < NCHUNKS; i++) {
        const int o = i & (OUT_STAGES - 1);
        const uint32_t mbar = sbase + SMEM_MBAR + s * 8;

        // 1) Wait for input chunk i, pull this thread's column to registers.
        mbar_wait(mbar, (uint32_t)parity);

        const float* sin = (const float*)(smem + SMEM_IN + s * CH_BYTES);
        float xv[CHUNK_T];
        #pragma unroll
        for (int u = 0; u < CHUNK_T; u++)
            xv[u] = sin[u * C + c];

        // 2) One sync covers: (a) all threads consumed smem-in stage s,
        //    (b) tid0's drain of the out-buffer we're about to overwrite.
        if (tid == 0)
            asm volatile("cp.async.bulk.wait_group.read 1;" ::: "memory");
        __syncthreads();

        // 3) Refill the consumed in-stage immediately (loads run during compute).
        if (tid == 0) {
            const int nxt = i + IN_STAGES;
            if (nxt < NCHUNKS) {
                mbar_expect_tx(mbar, CH_BYTES);
                bulk_load(sbase + SMEM_IN + s * CH_BYTES,
                          xslab + (size_t)nxt * CHUNK_T * C, CH_BYTES, mbar);
            }
        }

        // 4) Serial recurrence, spikes into the out smem buffer.
        float* sout = (float*)(smem + SMEM_OUT + o * CH_BYTES);
        #pragma unroll
        for (int u = 0; u < CHUNK_T; u++) {
            v = fmaxf(0.0f, xv[u] + (v < 1.0f ? d * v : 0.0f));
            sout[u * C + c] = (v > 1.0f) ? 1.0f : 0.0f;
        }

        __syncthreads();   // all spikes for chunk i in smem

        // 5) Bulk-store the chunk: one 40KB fully-contiguous write burst.
        if (tid == 0) {
            asm volatile("fence.proxy.async.shared::cta;" ::: "memory");
            bulk_store(oslab + (size_t)i * CHUNK_T * C,
                       sbase + SMEM_OUT + o * CH_BYTES, CH_BYTES);
            asm volatile("cp.async.bulk.commit_group;" ::: "memory");
        }

        if (++s == IN_STAGES) { s = 0; parity ^= 1; }
    }

    if (tid == 0)
        asm volatile("cp.async.bulk.wait_group 0;" ::: "memory");
}

extern "C" void kernel_launch(void* const* d_in, const int* in_sizes, int n_in,
                              void* d_out, int out_size)
{
    const float* x  = (const float*)d_in[0];   // x [B,T,C]
    const float* wl = (const float*)d_in[1];   // w_leak [C]
    float* out      = (float*)d_out;

    cudaFuncSetAttribute(lif_kernel, cudaFuncAttributeMaxDynamicSharedMemorySize,
                         (int)SMEM_TOTAL);
    lif_kernel<<<B, THREADS, SMEM_TOTAL>>>(x, wl, out);
}